// round 1
// baseline (speedup 1.0000x reference)
#include <cuda_runtime.h>

#define NQ_MAX 50000
#define NC 128
#define NG 8
#define NS 16

// Scratch for projected Q, K, V (fp32). 3 x 25.6 MB = 76.8 MB.
__device__ float g_q[NQ_MAX * NC];
__device__ float g_k[NQ_MAX * NC];
__device__ float g_v[NQ_MAX * NC];

// ---------------------------------------------------------------------------
// Projection GEMM: Y[m,c] = sum_k X[m,k] * W[c,k] + b[c]
// BM=128, BN=128(=C), BK=16, 256 threads, 8x8 per-thread tile.
// blockIdx.y selects which projection (0=Q, 1=K, 2=V).
// ---------------------------------------------------------------------------
__global__ void __launch_bounds__(256) proj_kernel(
    const float* __restrict__ x, const float* __restrict__ x2,
    const float* __restrict__ Wq, const float* __restrict__ bq,
    const float* __restrict__ Wk, const float* __restrict__ bk,
    const float* __restrict__ Wv, const float* __restrict__ bv,
    int n, int n2)
{
    const float *X, *W, *bias;
    float* Y;
    int M;
    if (blockIdx.y == 0)      { X = x;  W = Wq; bias = bq; Y = g_q; M = n;  }
    else if (blockIdx.y == 1) { X = x2; W = Wk; bias = bk; Y = g_k; M = n2; }
    else                      { X = x2; W = Wv; bias = bv; Y = g_v; M = n2; }

    __shared__ float As[16][128];   // [k][m]
    __shared__ float Bs[16][128];   // [k][c]

    const int t = threadIdx.x;
    const int block_m = blockIdx.x * 128;
    if (block_m >= M) return;

    const int tm = (t >> 4) << 3;   // 0..120
    const int tn = (t & 15) << 3;   // 0..120

    float acc[8][8];
#pragma unroll
    for (int i = 0; i < 8; i++)
#pragma unroll
        for (int j = 0; j < 8; j++) acc[i][j] = 0.f;

    for (int k0 = 0; k0 < 128; k0 += 16) {
#pragma unroll
        for (int it = 0; it < 2; it++) {
            int r  = (it << 6) + (t >> 2);   // 0..127
            int kc = (t & 3) << 2;           // 0,4,8,12
            int gr = block_m + r;
            float4 xv = make_float4(0.f, 0.f, 0.f, 0.f);
            if (gr < M) xv = *(const float4*)(X + (size_t)gr * 128 + k0 + kc);
            As[kc + 0][r] = xv.x; As[kc + 1][r] = xv.y;
            As[kc + 2][r] = xv.z; As[kc + 3][r] = xv.w;
            float4 wv = *(const float4*)(W + (size_t)r * 128 + k0 + kc);
            Bs[kc + 0][r] = wv.x; Bs[kc + 1][r] = wv.y;
            Bs[kc + 2][r] = wv.z; Bs[kc + 3][r] = wv.w;
        }
        __syncthreads();
#pragma unroll
        for (int k = 0; k < 16; k++) {
            float a[8], b[8];
            *(float4*)&a[0] = *(const float4*)&As[k][tm];
            *(float4*)&a[4] = *(const float4*)&As[k][tm + 4];
            *(float4*)&b[0] = *(const float4*)&Bs[k][tn];
            *(float4*)&b[4] = *(const float4*)&Bs[k][tn + 4];
#pragma unroll
            for (int i = 0; i < 8; i++)
#pragma unroll
                for (int j = 0; j < 8; j++)
                    acc[i][j] = fmaf(a[i], b[j], acc[i][j]);
        }
        __syncthreads();
    }

    float bl[8];
#pragma unroll
    for (int j = 0; j < 8; j++) bl[j] = bias[tn + j];

#pragma unroll
    for (int i = 0; i < 8; i++) {
        int gr = block_m + tm + i;
        if (gr < M) {
            float4 o0, o1;
            o0.x = acc[i][0] + bl[0]; o0.y = acc[i][1] + bl[1];
            o0.z = acc[i][2] + bl[2]; o0.w = acc[i][3] + bl[3];
            o1.x = acc[i][4] + bl[4]; o1.y = acc[i][5] + bl[5];
            o1.z = acc[i][6] + bl[6]; o1.w = acc[i][7] + bl[7];
            *(float4*)(Y + (size_t)gr * 128 + tn)     = o0;
            *(float4*)(Y + (size_t)gr * 128 + tn + 4) = o1;
        }
    }
}

// ---------------------------------------------------------------------------
// Fused gather + positional MLP + grouped attention.
// One warp per query. Lane l handles channels [4l, 4l+4), group g = l>>2
// (4 lanes per group, 16 channels per group).
// logits expansion: sum_c (k_c+prk)(q_c+prq)
//   = k.q + prk*sum(q) + prq*sum(k) + 16*prk*prq
// ---------------------------------------------------------------------------
__global__ void __launch_bounds__(256) attn_kernel(
    const float* __restrict__ p, const float* __restrict__ p2,
    const int* __restrict__ idx,
    const float* __restrict__ W1, const float* __restrict__ b1,
    const float* __restrict__ bng, const float* __restrict__ bnb,
    const float* __restrict__ bnm, const float* __restrict__ bnv,
    const float* __restrict__ W2, const float* __restrict__ b2,
    float* __restrict__ out, int n)
{
    __shared__ float sA[9];        // BN-folded conv1 weights
    __shared__ float sc[3];        // BN-folded conv1 bias
    __shared__ float sW2[16][3];
    __shared__ float sb2[16];

    const int t = threadIdx.x;
    if (t < 9) {
        int r = t / 3;
        float s = bng[r] * rsqrtf(bnv[r] + 1e-5f);
        sA[t] = s * W1[t];
    }
    if (t < 3) sc[t] = bng[t] * rsqrtf(bnv[t] + 1e-5f) * (b1[t] - bnm[t]) + bnb[t];
    if (t < 48) sW2[t / 3][t % 3] = W2[t];
    if (t < 16) sb2[t] = b2[t];
    __syncthreads();

    const int warp = t >> 5;
    const int lane = t & 31;
    const int i = blockIdx.x * 8 + warp;
    if (i >= n) return;

    const int g = lane >> 2;

    const float4 q4 = *(const float4*)(g_q + (size_t)i * 128 + lane * 4);
    float qs = q4.x + q4.y + q4.z + q4.w;
    qs += __shfl_xor_sync(0xffffffffu, qs, 1);
    qs += __shfl_xor_sync(0xffffffffu, qs, 2);

    const float px = p[i * 3 + 0], py = p[i * 3 + 1], pz = p[i * 3 + 2];

    int nb[16];
    {
        const int4* ip = (const int4*)(idx + (size_t)i * 16);
#pragma unroll
        for (int s4 = 0; s4 < 4; s4++) {
            int4 v = ip[s4];
            nb[s4 * 4 + 0] = v.x; nb[s4 * 4 + 1] = v.y;
            nb[s4 * 4 + 2] = v.z; nb[s4 * 4 + 3] = v.w;
        }
    }

    float logit[16];
#pragma unroll
    for (int s = 0; s < 16; s++) {
        const int j = nb[s];
        const float4 k4 = *(const float4*)(g_k + (size_t)j * 128 + lane * 4);
        float kq = k4.x * q4.x + k4.y * q4.y + k4.z * q4.z + k4.w * q4.w;
        float ks = k4.x + k4.y + k4.z + k4.w;
        kq += __shfl_xor_sync(0xffffffffu, kq, 1);
        ks += __shfl_xor_sync(0xffffffffu, ks, 1);
        kq += __shfl_xor_sync(0xffffffffu, kq, 2);
        ks += __shfl_xor_sync(0xffffffffu, ks, 2);

        const float rx = p2[j * 3 + 0] - px;
        const float ry = p2[j * 3 + 1] - py;
        const float rz = p2[j * 3 + 2] - pz;
        const float h0 = fmaxf(sA[0] * rx + sA[1] * ry + sA[2] * rz + sc[0], 0.f);
        const float h1 = fmaxf(sA[3] * rx + sA[4] * ry + sA[5] * rz + sc[1], 0.f);
        const float h2 = fmaxf(sA[6] * rx + sA[7] * ry + sA[8] * rz + sc[2], 0.f);
        const float prq = sW2[g][0] * h0 + sW2[g][1] * h1 + sW2[g][2] * h2 + sb2[g];
        const float prk = sW2[8 + g][0] * h0 + sW2[8 + g][1] * h1 + sW2[8 + g][2] * h2 + sb2[8 + g];

        logit[s] = 0.25f * (kq + prk * qs + prq * ks + 16.f * prk * prq);
    }

    // softmax over neighbors (replicated across the 4 lanes of a group)
    float mx = logit[0];
#pragma unroll
    for (int s = 1; s < 16; s++) mx = fmaxf(mx, logit[s]);
    float denom = 0.f;
#pragma unroll
    for (int s = 0; s < 16; s++) {
        logit[s] = __expf(logit[s] - mx);
        denom += logit[s];
    }
    const float inv = 1.f / denom;

    float4 o = make_float4(0.f, 0.f, 0.f, 0.f);
#pragma unroll
    for (int s = 0; s < 16; s++) {
        const float w = logit[s] * inv;
        const float4 v4 = *(const float4*)(g_v + (size_t)nb[s] * 128 + lane * 4);
        o.x = fmaf(w, v4.x, o.x);
        o.y = fmaf(w, v4.y, o.y);
        o.z = fmaf(w, v4.z, o.z);
        o.w = fmaf(w, v4.w, o.w);
    }
    *(float4*)(out + (size_t)i * 128 + lane * 4) = o;
}

extern "C" void kernel_launch(void* const* d_in, const int* in_sizes, int n_in,
                              void* d_out, int out_size)
{
    const float* p   = (const float*)d_in[0];
    const float* x   = (const float*)d_in[1];
    const float* p2  = (const float*)d_in[2];
    const float* x2  = (const float*)d_in[3];
    const int*   idx = (const int*)d_in[4];
    const float* Wq  = (const float*)d_in[5];
    const float* bq  = (const float*)d_in[6];
    const float* Wk  = (const float*)d_in[7];
    const float* bk  = (const float*)d_in[8];
    const float* Wv  = (const float*)d_in[9];
    const float* bv  = (const float*)d_in[10];
    const float* W1  = (const float*)d_in[11];
    const float* b1  = (const float*)d_in[12];
    const float* bng = (const float*)d_in[13];
    const float* bnb = (const float*)d_in[14];
    const float* bnm = (const float*)d_in[15];
    const float* bnv = (const float*)d_in[16];
    const float* W2  = (const float*)d_in[17];
    const float* b2  = (const float*)d_in[18];
    float* out = (float*)d_out;

    const int n  = in_sizes[1] / NC;
    const int n2 = in_sizes[3] / NC;
    const int mmax = n > n2 ? n : n2;

    dim3 pg((mmax + 127) / 128, 3);
    proj_kernel<<<pg, 256>>>(x, x2, Wq, bq, Wk, bk, Wv, bv, n, n2);
    attn_kernel<<<(n + 7) / 8, 256>>>(p, p2, idx, W1, b1, bng, bnb, bnm, bnv,
                                      W2, b2, out, n);
}

// round 2
// speedup vs baseline: 1.0001x; 1.0001x over previous
#include <cuda_runtime.h>

#define NQ_MAX 50000
#define NC 128
#define NG 8
#define NS 16

// Scratch for projected Q, K, V (fp32). 3 x 25.6 MB = 76.8 MB.
__device__ float g_q[NQ_MAX * NC];
__device__ float g_k[NQ_MAX * NC];
__device__ float g_v[NQ_MAX * NC];

// ---------------------------------------------------------------------------
// Projection GEMM: Y[m,c] = sum_k X[m,k] * W[c,k] + b[c]
// BM=128, BN=128(=C), BK=16, 256 threads, 8x8 per-thread tile.
// blockIdx.y selects which projection (0=Q, 1=K, 2=V).
// ---------------------------------------------------------------------------
__global__ void __launch_bounds__(256) proj_kernel(
    const float* __restrict__ x, const float* __restrict__ x2,
    const float* __restrict__ Wq, const float* __restrict__ bq,
    const float* __restrict__ Wk, const float* __restrict__ bk,
    const float* __restrict__ Wv, const float* __restrict__ bv,
    int n, int n2)
{
    const float *X, *W, *bias;
    float* Y;
    int M;
    if (blockIdx.y == 0)      { X = x;  W = Wq; bias = bq; Y = g_q; M = n;  }
    else if (blockIdx.y == 1) { X = x2; W = Wk; bias = bk; Y = g_k; M = n2; }
    else                      { X = x2; W = Wv; bias = bv; Y = g_v; M = n2; }

    __shared__ float As[16][128];   // [k][m]
    __shared__ float Bs[16][128];   // [k][c]

    const int t = threadIdx.x;
    const int block_m = blockIdx.x * 128;
    if (block_m >= M) return;

    const int tm = (t >> 4) << 3;   // 0..120
    const int tn = (t & 15) << 3;   // 0..120

    float acc[8][8];
#pragma unroll
    for (int i = 0; i < 8; i++)
#pragma unroll
        for (int j = 0; j < 8; j++) acc[i][j] = 0.f;

    for (int k0 = 0; k0 < 128; k0 += 16) {
#pragma unroll
        for (int it = 0; it < 2; it++) {
            int r  = (it << 6) + (t >> 2);   // 0..127
            int kc = (t & 3) << 2;           // 0,4,8,12
            int gr = block_m + r;
            float4 xv = make_float4(0.f, 0.f, 0.f, 0.f);
            if (gr < M) xv = *(const float4*)(X + (size_t)gr * 128 + k0 + kc);
            As[kc + 0][r] = xv.x; As[kc + 1][r] = xv.y;
            As[kc + 2][r] = xv.z; As[kc + 3][r] = xv.w;
            float4 wv = *(const float4*)(W + (size_t)r * 128 + k0 + kc);
            Bs[kc + 0][r] = wv.x; Bs[kc + 1][r] = wv.y;
            Bs[kc + 2][r] = wv.z; Bs[kc + 3][r] = wv.w;
        }
        __syncthreads();
#pragma unroll
        for (int k = 0; k < 16; k++) {
            float a[8], b[8];
            *(float4*)&a[0] = *(const float4*)&As[k][tm];
            *(float4*)&a[4] = *(const float4*)&As[k][tm + 4];
            *(float4*)&b[0] = *(const float4*)&Bs[k][tn];
            *(float4*)&b[4] = *(const float4*)&Bs[k][tn + 4];
#pragma unroll
            for (int i = 0; i < 8; i++)
#pragma unroll
                for (int j = 0; j < 8; j++)
                    acc[i][j] = fmaf(a[i], b[j], acc[i][j]);
        }
        __syncthreads();
    }

    float bl[8];
#pragma unroll
    for (int j = 0; j < 8; j++) bl[j] = bias[tn + j];

#pragma unroll
    for (int i = 0; i < 8; i++) {
        int gr = block_m + tm + i;
        if (gr < M) {
            float4 o0, o1;
            o0.x = acc[i][0] + bl[0]; o0.y = acc[i][1] + bl[1];
            o0.z = acc[i][2] + bl[2]; o0.w = acc[i][3] + bl[3];
            o1.x = acc[i][4] + bl[4]; o1.y = acc[i][5] + bl[5];
            o1.z = acc[i][6] + bl[6]; o1.w = acc[i][7] + bl[7];
            *(float4*)(Y + (size_t)gr * 128 + tn)     = o0;
            *(float4*)(Y + (size_t)gr * 128 + tn + 4) = o1;
        }
    }
}

// ---------------------------------------------------------------------------
// Fused gather + positional MLP + grouped attention.
// One warp per query. Lane l handles channels [4l, 4l+4), group g = l>>2
// (4 lanes per group, 16 channels per group).
// logits expansion: sum_c (k_c+prk)(q_c+prq)
//   = k.q + prk*sum(q) + prq*sum(k) + 16*prk*prq
// ---------------------------------------------------------------------------
__global__ void __launch_bounds__(256) attn_kernel(
    const float* __restrict__ p, const float* __restrict__ p2,
    const int* __restrict__ idx,
    const float* __restrict__ W1, const float* __restrict__ b1,
    const float* __restrict__ bng, const float* __restrict__ bnb,
    const float* __restrict__ bnm, const float* __restrict__ bnv,
    const float* __restrict__ W2, const float* __restrict__ b2,
    float* __restrict__ out, int n)
{
    __shared__ float sA[9];        // BN-folded conv1 weights
    __shared__ float sc[3];        // BN-folded conv1 bias
    __shared__ float sW2[16][3];
    __shared__ float sb2[16];

    const int t = threadIdx.x;
    if (t < 9) {
        int r = t / 3;
        float s = bng[r] * rsqrtf(bnv[r] + 1e-5f);
        sA[t] = s * W1[t];
    }
    if (t < 3) sc[t] = bng[t] * rsqrtf(bnv[t] + 1e-5f) * (b1[t] - bnm[t]) + bnb[t];
    if (t < 48) sW2[t / 3][t % 3] = W2[t];
    if (t < 16) sb2[t] = b2[t];
    __syncthreads();

    const int warp = t >> 5;
    const int lane = t & 31;
    const int i = blockIdx.x * 8 + warp;
    if (i >= n) return;

    const int g = lane >> 2;

    const float4 q4 = *(const float4*)(g_q + (size_t)i * 128 + lane * 4);
    float qs = q4.x + q4.y + q4.z + q4.w;
    qs += __shfl_xor_sync(0xffffffffu, qs, 1);
    qs += __shfl_xor_sync(0xffffffffu, qs, 2);

    const float px = p[i * 3 + 0], py = p[i * 3 + 1], pz = p[i * 3 + 2];

    int nb[16];
    {
        const int4* ip = (const int4*)(idx + (size_t)i * 16);
#pragma unroll
        for (int s4 = 0; s4 < 4; s4++) {
            int4 v = ip[s4];
            nb[s4 * 4 + 0] = v.x; nb[s4 * 4 + 1] = v.y;
            nb[s4 * 4 + 2] = v.z; nb[s4 * 4 + 3] = v.w;
        }
    }

    float logit[16];
#pragma unroll
    for (int s = 0; s < 16; s++) {
        const int j = nb[s];
        const float4 k4 = *(const float4*)(g_k + (size_t)j * 128 + lane * 4);
        float kq = k4.x * q4.x + k4.y * q4.y + k4.z * q4.z + k4.w * q4.w;
        float ks = k4.x + k4.y + k4.z + k4.w;
        kq += __shfl_xor_sync(0xffffffffu, kq, 1);
        ks += __shfl_xor_sync(0xffffffffu, ks, 1);
        kq += __shfl_xor_sync(0xffffffffu, kq, 2);
        ks += __shfl_xor_sync(0xffffffffu, ks, 2);

        const float rx = p2[j * 3 + 0] - px;
        const float ry = p2[j * 3 + 1] - py;
        const float rz = p2[j * 3 + 2] - pz;
        const float h0 = fmaxf(sA[0] * rx + sA[1] * ry + sA[2] * rz + sc[0], 0.f);
        const float h1 = fmaxf(sA[3] * rx + sA[4] * ry + sA[5] * rz + sc[1], 0.f);
        const float h2 = fmaxf(sA[6] * rx + sA[7] * ry + sA[8] * rz + sc[2], 0.f);
        const float prq = sW2[g][0] * h0 + sW2[g][1] * h1 + sW2[g][2] * h2 + sb2[g];
        const float prk = sW2[8 + g][0] * h0 + sW2[8 + g][1] * h1 + sW2[8 + g][2] * h2 + sb2[8 + g];

        logit[s] = 0.25f * (kq + prk * qs + prq * ks + 16.f * prk * prq);
    }

    // softmax over neighbors (replicated across the 4 lanes of a group)
    float mx = logit[0];
#pragma unroll
    for (int s = 1; s < 16; s++) mx = fmaxf(mx, logit[s]);
    float denom = 0.f;
#pragma unroll
    for (int s = 0; s < 16; s++) {
        logit[s] = __expf(logit[s] - mx);
        denom += logit[s];
    }
    const float inv = 1.f / denom;

    float4 o = make_float4(0.f, 0.f, 0.f, 0.f);
#pragma unroll
    for (int s = 0; s < 16; s++) {
        const float w = logit[s] * inv;
        const float4 v4 = *(const float4*)(g_v + (size_t)nb[s] * 128 + lane * 4);
        o.x = fmaf(w, v4.x, o.x);
        o.y = fmaf(w, v4.y, o.y);
        o.z = fmaf(w, v4.z, o.z);
        o.w = fmaf(w, v4.w, o.w);
    }
    *(float4*)(out + (size_t)i * 128 + lane * 4) = o;
}

extern "C" void kernel_launch(void* const* d_in, const int* in_sizes, int n_in,
                              void* d_out, int out_size)
{
    const float* p   = (const float*)d_in[0];
    const float* x   = (const float*)d_in[1];
    const float* p2  = (const float*)d_in[2];
    const float* x2  = (const float*)d_in[3];
    const int*   idx = (const int*)d_in[4];
    const float* Wq  = (const float*)d_in[5];
    const float* bq  = (const float*)d_in[6];
    const float* Wk  = (const float*)d_in[7];
    const float* bk  = (const float*)d_in[8];
    const float* Wv  = (const float*)d_in[9];
    const float* bv  = (const float*)d_in[10];
    const float* W1  = (const float*)d_in[11];
    const float* b1  = (const float*)d_in[12];
    const float* bng = (const float*)d_in[13];
    const float* bnb = (const float*)d_in[14];
    const float* bnm = (const float*)d_in[15];
    const float* bnv = (const float*)d_in[16];
    const float* W2  = (const float*)d_in[17];
    const float* b2  = (const float*)d_in[18];
    float* out = (float*)d_out;

    const int n  = in_sizes[1] / NC;
    const int n2 = in_sizes[3] / NC;
    const int mmax = n > n2 ? n : n2;

    dim3 pg((mmax + 127) / 128, 3);
    proj_kernel<<<pg, 256>>>(x, x2, Wq, bq, Wk, bk, Wv, bv, n, n2);
    attn_kernel<<<(n + 7) / 8, 256>>>(p, p2, idx, W1, b1, bng, bnb, bnm, bnv,
                                      W2, b2, out, n);
}